// round 1
// baseline (speedup 1.0000x reference)
#include <cuda_runtime.h>
#include <math.h>
#include <stdint.h>

#define NUM_TOK 8192
#define HID     1024
#define INTERD  2816
#define NEXP    8
#define NROWS   (NUM_TOK * 2)            // 16384 (token, slot) rows
#define BM      128
#define M_MAX   (NROWS + NEXP * BM)      // 17408, segments padded to BM
#define NTILES  (M_MAX / BM)             // 136
#define N1      (2 * INTERD)             // 5632

// ---------------- scratch (device globals; no allocations allowed) ----------
__device__ int   g_perm_token[M_MAX];
__device__ float g_perm_w[M_MAX];
__device__ int   g_counts[NEXP];
__device__ int   g_offsets[NEXP];
__device__ int   g_fill[NEXP];
__device__ int   g_tile_expert[NTILES];
__device__ int   g_topk_i[NROWS];
__device__ float g_topk_w[NROWS];
__device__ float g_h[(size_t)M_MAX * N1];      // GEMM1 output (gate|up)
__device__ float g_act[(size_t)M_MAX * INTERD];// silu(gate)*up

// ---------------- init: zero counters, poison perm, zero output -------------
__global__ void init_kernel(float* __restrict__ out) {
    int i = blockIdx.x * blockDim.x + threadIdx.x;
    int stride = gridDim.x * blockDim.x;
    if (i < NEXP) { g_counts[i] = 0; g_fill[i] = 0; }
    if (i < NTILES) g_tile_expert[i] = 0;
    for (int r = i; r < M_MAX; r += stride) { g_perm_token[r] = -1; g_perm_w[r] = 0.f; }
    for (size_t j = i; j < (size_t)NUM_TOK * HID; j += stride) out[j] = 0.f;
}

// ---------------- gating: one warp per token ------------------------------
__global__ void gate_kernel(const float* __restrict__ x, const float* __restrict__ gw) {
    int warp = (blockIdx.x * blockDim.x + threadIdx.x) >> 5;
    int lane = threadIdx.x & 31;
    if (warp >= NUM_TOK) return;
    const float* xr = x + (size_t)warp * HID;
    float acc[NEXP];
#pragma unroll
    for (int e = 0; e < NEXP; e++) acc[e] = 0.f;
    for (int h = lane; h < HID; h += 32) {
        float xv = xr[h];
#pragma unroll
        for (int e = 0; e < NEXP; e++) acc[e] += xv * gw[e * HID + h];
    }
#pragma unroll
    for (int e = 0; e < NEXP; e++) {
#pragma unroll
        for (int o = 16; o > 0; o >>= 1)
            acc[e] += __shfl_xor_sync(0xffffffffu, acc[e], o);
    }
    if (lane == 0) {
        int i1 = 0;
#pragma unroll
        for (int e = 1; e < NEXP; e++) if (acc[e] > acc[i1]) i1 = e;
        int i2 = (i1 == 0) ? 1 : 0;
#pragma unroll
        for (int e = 0; e < NEXP; e++) if (e != i1 && acc[e] > acc[i2]) i2 = e;
        // softmax top-2 renormalized == 2-way softmax over the two logits
        float d  = expf(acc[i2] - acc[i1]);
        float wa = 1.f / (1.f + d);
        float wb = d / (1.f + d);
        g_topk_i[warp * 2]     = i1;
        g_topk_i[warp * 2 + 1] = i2;
        g_topk_w[warp * 2]     = wa;
        g_topk_w[warp * 2 + 1] = wb;
        atomicAdd(&g_counts[i1], 1);
        atomicAdd(&g_counts[i2], 1);
    }
}

// ---------------- segment offsets + per-tile expert map (1 thread, tiny) ---
__global__ void scan_kernel() {
    int off = 0;
    for (int e = 0; e < NEXP; e++) {
        g_offsets[e] = off;
        int padded = ((g_counts[e] + BM - 1) / BM) * BM;
        for (int t = 0; t < padded / BM; t++) g_tile_expert[off / BM + t] = e;
        off += padded;
    }
}

// ---------------- scatter (token,slot) rows into expert segments -----------
__global__ void scatter_kernel() {
    int i = blockIdx.x * blockDim.x + threadIdx.x;
    if (i >= NROWS) return;
    int e = g_topk_i[i];
    int pos = g_offsets[e] + atomicAdd(&g_fill[e], 1);
    g_perm_token[pos] = i >> 1;
    g_perm_w[pos] = g_topk_w[i];
}

// ---------------- GEMM1: h[row] = x[token(row)] @ w1[e]  (M x 1024 x 5632) --
__global__ void __launch_bounds__(256) gemm1_kernel(const float* __restrict__ x,
                                                    const float* __restrict__ w1) {
    __shared__ float As[8][BM];
    __shared__ float Bs[8][128];
    const int mt = blockIdx.y, nt = blockIdx.x;
    const int e = g_tile_expert[mt];
    const float* B = w1 + (size_t)e * HID * N1 + (size_t)nt * 128;
    const int tid = threadIdx.x;

    const int arow = tid >> 1;
    const int akk  = (tid & 1) * 4;
    const int grow = mt * BM + arow;
    const int tok  = g_perm_token[grow];
    const float* Aptr = (tok >= 0) ? (x + (size_t)tok * HID) : nullptr;

    const int bk = tid >> 5;
    const int bn = (tid & 31) * 4;
    const int tx = tid & 15, ty = tid >> 4;

    float acc[8][8];
#pragma unroll
    for (int i = 0; i < 8; i++)
#pragma unroll
        for (int j = 0; j < 8; j++) acc[i][j] = 0.f;

    for (int k0 = 0; k0 < HID; k0 += 8) {
        float4 av = make_float4(0.f, 0.f, 0.f, 0.f);
        if (Aptr) av = *(const float4*)(Aptr + k0 + akk);
        As[akk + 0][arow] = av.x; As[akk + 1][arow] = av.y;
        As[akk + 2][arow] = av.z; As[akk + 3][arow] = av.w;
        *(float4*)&Bs[bk][bn] = *(const float4*)(B + (size_t)(k0 + bk) * N1 + bn);
        __syncthreads();
#pragma unroll
        for (int k = 0; k < 8; k++) {
            float a[8], b[8];
#pragma unroll
            for (int i = 0; i < 8; i++) a[i] = As[k][ty * 8 + i];
#pragma unroll
            for (int j = 0; j < 8; j++) b[j] = Bs[k][tx * 8 + j];
#pragma unroll
            for (int i = 0; i < 8; i++)
#pragma unroll
                for (int j = 0; j < 8; j++) acc[i][j] += a[i] * b[j];
        }
        __syncthreads();
    }
#pragma unroll
    for (int i = 0; i < 8; i++) {
        size_t row = (size_t)(mt * BM + ty * 8 + i);
        float* cp = g_h + row * N1 + nt * 128 + tx * 8;
        *(float4*)(cp)     = make_float4(acc[i][0], acc[i][1], acc[i][2], acc[i][3]);
        *(float4*)(cp + 4) = make_float4(acc[i][4], acc[i][5], acc[i][6], acc[i][7]);
    }
}

// ---------------- activation: silu(gate) * up ------------------------------
__global__ void act_kernel() {
    size_t r = blockIdx.x;
    const float* hr = g_h + r * N1;
    float* ar = g_act + r * INTERD;
    for (int i = threadIdx.x; i < INTERD; i += blockDim.x) {
        float g = hr[i];
        float u = hr[INTERD + i];
        ar[i] = (g / (1.f + expf(-g))) * u;
    }
}

// ---------------- GEMM2: out[token] += w * (act[row] @ w2[e]) ---------------
__global__ void __launch_bounds__(256) gemm2_kernel(const float* __restrict__ w2,
                                                    float* __restrict__ out) {
    __shared__ float As[8][BM];
    __shared__ float Bs[8][128];
    const int mt = blockIdx.y, nt = blockIdx.x;
    const int e = g_tile_expert[mt];
    const float* B = w2 + (size_t)e * INTERD * HID + (size_t)nt * 128;
    const int tid = threadIdx.x;

    const int arow = tid >> 1;
    const int akk  = (tid & 1) * 4;
    const float* Aptr = g_act + (size_t)(mt * BM + arow) * INTERD;

    const int bk = tid >> 5;
    const int bn = (tid & 31) * 4;
    const int tx = tid & 15, ty = tid >> 4;

    float acc[8][8];
#pragma unroll
    for (int i = 0; i < 8; i++)
#pragma unroll
        for (int j = 0; j < 8; j++) acc[i][j] = 0.f;

    for (int k0 = 0; k0 < INTERD; k0 += 8) {
        float4 av = *(const float4*)(Aptr + k0 + akk);
        As[akk + 0][arow] = av.x; As[akk + 1][arow] = av.y;
        As[akk + 2][arow] = av.z; As[akk + 3][arow] = av.w;
        *(float4*)&Bs[bk][bn] = *(const float4*)(B + (size_t)(k0 + bk) * HID + bn);
        __syncthreads();
#pragma unroll
        for (int k = 0; k < 8; k++) {
            float a[8], b[8];
#pragma unroll
            for (int i = 0; i < 8; i++) a[i] = As[k][ty * 8 + i];
#pragma unroll
            for (int j = 0; j < 8; j++) b[j] = Bs[k][tx * 8 + j];
#pragma unroll
            for (int i = 0; i < 8; i++)
#pragma unroll
                for (int j = 0; j < 8; j++) acc[i][j] += a[i] * b[j];
        }
        __syncthreads();
    }
#pragma unroll
    for (int i = 0; i < 8; i++) {
        int row = mt * BM + ty * 8 + i;
        int tok = g_perm_token[row];
        if (tok < 0) continue;
        float w = g_perm_w[row];
        float* op = out + (size_t)tok * HID + nt * 128 + tx * 8;
#pragma unroll
        for (int j = 0; j < 8; j++) atomicAdd(op + j, w * acc[i][j]);
    }
}

// ---------------- launch ----------------------------------------------------
extern "C" void kernel_launch(void* const* d_in, const int* in_sizes, int n_in,
                              void* d_out, int out_size) {
    const float* x  = (const float*)d_in[0];   // [4,2048,1024]
    const float* gw = (const float*)d_in[1];   // [8,1024]
    const float* w1 = (const float*)d_in[2];   // [8,1024,5632]
    const float* w2 = (const float*)d_in[3];   // [8,2816,1024]
    float* out = (float*)d_out;                // [4,2048,1024]

    init_kernel<<<256, 256>>>(out);
    gate_kernel<<<NUM_TOK / 8, 256>>>(x, gw);
    scan_kernel<<<1, 1>>>();
    scatter_kernel<<<NROWS / 256, 256>>>();
    gemm1_kernel<<<dim3(N1 / 128, NTILES), 256>>>(x, w1);
    act_kernel<<<M_MAX, 256>>>();
    gemm2_kernel<<<dim3(HID / 128, NTILES), 256>>>(w2, out);
}

// round 3
// speedup vs baseline: 4.9287x; 4.9287x over previous
#include <cuda_runtime.h>
#include <cuda_fp16.h>
#include <math.h>
#include <stdint.h>

#define NUM_TOK 8192
#define HID     1024
#define INTERD  2816
#define NEXP    8
#define NROWS   (NUM_TOK * 2)
#define BM      128
#define M_MAX   (NROWS + NEXP * BM)      // 17408
#define NTILES  (M_MAX / BM)             // 136
#define N1      (2 * INTERD)             // 5632

#define KSTEP   32                        // k per pipeline stage (halves)
#define ROWH    40                        // padded row length in halves (80B)
#define TB      (128 * ROWH * 2)          // 10240 bytes per 128x32 tile
#define STG1    (3 * TB)                  // A, Bgate, Bup
#define STG2    (2 * TB)                  // A, B
#define S1      3                         // stages gemm1
#define S2      4                         // stages gemm2
#define NCH1    (HID / KSTEP)             // 32
#define NCH2    (INTERD / KSTEP)          // 88

// ---------------- device scratch ----------------
__device__ int   g_perm_token[M_MAX];
__device__ float g_perm_w[M_MAX];
__device__ int   g_counts[NEXP];
__device__ int   g_offsets[NEXP];
__device__ int   g_fill[NEXP];
__device__ int   g_tile_expert[NTILES];
__device__ int   g_topk_i[NROWS];
__device__ float g_topk_w[NROWS];

__device__ __half g_x16[(size_t)NUM_TOK * HID];
__device__ __half g_w1t[(size_t)NEXP * N1 * HID];     // [e][n][k]
__device__ __half g_w2t[(size_t)NEXP * HID * INTERD]; // [e][h][i]
__device__ __half g_act[(size_t)M_MAX * INTERD];      // [row][i]

// ---------------- ptx helpers ----------------
__device__ __forceinline__ uint32_t s2u(const void* p) {
    uint32_t a;
    asm("{ .reg .u64 t; cvta.to.shared.u64 t, %1; cvt.u32.u64 %0, t; }" : "=r"(a) : "l"(p));
    return a;
}
__device__ __forceinline__ void ldsm4(uint32_t* r, uint32_t addr) {
    asm volatile("ldmatrix.sync.aligned.m8n8.x4.shared.b16 {%0,%1,%2,%3}, [%4];"
                 : "=r"(r[0]), "=r"(r[1]), "=r"(r[2]), "=r"(r[3]) : "r"(addr));
}
__device__ __forceinline__ void mma16816(float* d, const uint32_t* a,
                                         uint32_t b0, uint32_t b1) {
    asm volatile(
        "mma.sync.aligned.m16n8k16.row.col.f32.f16.f16.f32 "
        "{%0,%1,%2,%3}, {%4,%5,%6,%7}, {%8,%9}, {%0,%1,%2,%3};"
        : "+f"(d[0]), "+f"(d[1]), "+f"(d[2]), "+f"(d[3])
        : "r"(a[0]), "r"(a[1]), "r"(a[2]), "r"(a[3]), "r"(b0), "r"(b1));
}
__device__ __forceinline__ void cp16(uint32_t dst, const void* src, int sz) {
    asm volatile("cp.async.cg.shared.global [%0], [%1], 16, %2;"
                 :: "r"(dst), "l"(src), "r"(sz));
}
#define CP_COMMIT() asm volatile("cp.async.commit_group;" ::: "memory")
#define CP_WAIT(n)  asm volatile("cp.async.wait_group %0;" :: "n"(n) : "memory")

// ---------------- small kernels (unchanged logic from R1) ----------------
__global__ void init_kernel(float* __restrict__ out) {
    int i = blockIdx.x * blockDim.x + threadIdx.x;
    int stride = gridDim.x * blockDim.x;
    if (i < NEXP) { g_counts[i] = 0; g_fill[i] = 0; }
    if (i < NTILES) g_tile_expert[i] = 0;
    for (int r = i; r < M_MAX; r += stride) { g_perm_token[r] = -1; g_perm_w[r] = 0.f; }
    for (size_t j = i; j < (size_t)NUM_TOK * HID; j += stride) out[j] = 0.f;
}

__global__ void convert_x_kernel(const float* __restrict__ x) {
    size_t i = (size_t)blockIdx.x * blockDim.x + threadIdx.x;
    size_t stride = (size_t)gridDim.x * blockDim.x;
    for (size_t j = i; j < (size_t)NUM_TOK * HID; j += stride)
        g_x16[j] = __float2half(x[j]);
}

// w1[e][k][n] -> w1t[e][n][k] fp16
__global__ void transpose_w1_kernel(const float* __restrict__ w1) {
    __shared__ float t[32][33];
    int e = blockIdx.z;
    int n0 = blockIdx.x * 32, k0 = blockIdx.y * 32;
    int tx = threadIdx.x, ty = threadIdx.y;
    const float* src = w1 + ((size_t)e * HID + k0) * N1 + n0;
    for (int i = ty; i < 32; i += 8) t[i][tx] = src[(size_t)i * N1 + tx];
    __syncthreads();
    size_t base = ((size_t)e * N1 + n0) * HID + k0;
    for (int i = ty; i < 32; i += 8)
        g_w1t[base + (size_t)i * HID + tx] = __float2half(t[tx][i]);
}

// w2[e][i][h] -> w2t[e][h][i] fp16
__global__ void transpose_w2_kernel(const float* __restrict__ w2) {
    __shared__ float t[32][33];
    int e = blockIdx.z;
    int i0 = blockIdx.x * 32, h0 = blockIdx.y * 32;
    int tx = threadIdx.x, ty = threadIdx.y;
    const float* src = w2 + ((size_t)e * INTERD + i0) * HID + h0;
    for (int i = ty; i < 32; i += 8) t[i][tx] = src[(size_t)i * HID + tx];
    __syncthreads();
    size_t base = ((size_t)e * HID + h0) * INTERD + i0;
    for (int i = ty; i < 32; i += 8)
        g_w2t[base + (size_t)i * INTERD + tx] = __float2half(t[tx][i]);
}

__global__ void gate_kernel(const float* __restrict__ x, const float* __restrict__ gw) {
    int warp = (blockIdx.x * blockDim.x + threadIdx.x) >> 5;
    int lane = threadIdx.x & 31;
    if (warp >= NUM_TOK) return;
    const float* xr = x + (size_t)warp * HID;
    float acc[NEXP];
#pragma unroll
    for (int e = 0; e < NEXP; e++) acc[e] = 0.f;
    for (int h = lane; h < HID; h += 32) {
        float xv = xr[h];
#pragma unroll
        for (int e = 0; e < NEXP; e++) acc[e] += xv * gw[e * HID + h];
    }
#pragma unroll
    for (int e = 0; e < NEXP; e++)
#pragma unroll
        for (int o = 16; o > 0; o >>= 1)
            acc[e] += __shfl_xor_sync(0xffffffffu, acc[e], o);
    if (lane == 0) {
        int i1 = 0;
#pragma unroll
        for (int e = 1; e < NEXP; e++) if (acc[e] > acc[i1]) i1 = e;
        int i2 = (i1 == 0) ? 1 : 0;
#pragma unroll
        for (int e = 0; e < NEXP; e++) if (e != i1 && acc[e] > acc[i2]) i2 = e;
        float d  = expf(acc[i2] - acc[i1]);
        float wa = 1.f / (1.f + d);
        float wb = d / (1.f + d);
        g_topk_i[warp * 2] = i1;     g_topk_i[warp * 2 + 1] = i2;
        g_topk_w[warp * 2] = wa;     g_topk_w[warp * 2 + 1] = wb;
        atomicAdd(&g_counts[i1], 1); atomicAdd(&g_counts[i2], 1);
    }
}

__global__ void scan_kernel() {
    int off = 0;
    for (int e = 0; e < NEXP; e++) {
        g_offsets[e] = off;
        int padded = ((g_counts[e] + BM - 1) / BM) * BM;
        for (int t = 0; t < padded / BM; t++) g_tile_expert[off / BM + t] = e;
        off += padded;
    }
}

__global__ void scatter_kernel() {
    int i = blockIdx.x * blockDim.x + threadIdx.x;
    if (i >= NROWS) return;
    int e = g_topk_i[i];
    int pos = g_offsets[e] + atomicAdd(&g_fill[e], 1);
    g_perm_token[pos] = i >> 1;
    g_perm_w[pos] = g_topk_w[i];
}

// =================== GEMM1: fused gate/up + SiLU epilogue ===================
// CTA: M=128 rows (one expert tile), N=128 cols of gate AND up. 512 threads,
// warp grid 4x4, warp tile 32x32 (x2 matrices).
__device__ __forceinline__ void g1_load(int c, int slot, uint32_t sb,
                                        const int* tok_s, int e, int nt, int tid) {
    const int k0 = c * KSTEP;
#pragma unroll
    for (int it = 0; it < 3; it++) {
        int u = it * 512 + tid;
        int tile = u >> 9, v = u & 511;
        int row = v >> 2, ch = v & 3;
        uint32_t dst = sb + slot * STG1 + tile * TB + row * (ROWH * 2) + ch * 16;
        const __half* src;
        int sz = 16;
        if (tile == 0) {
            int tok = tok_s[row];
            if (tok < 0) { sz = 0; tok = 0; }
            src = g_x16 + (size_t)tok * HID + k0 + ch * 8;
        } else {
            int nrow = nt * 128 + row + ((tile == 2) ? INTERD : 0);
            src = g_w1t + ((size_t)e * N1 + nrow) * HID + k0 + ch * 8;
        }
        cp16(dst, src, sz);
    }
    CP_COMMIT();
}

__global__ void __launch_bounds__(512, 1) gemm1_kernel() {
    extern __shared__ __align__(128) char dsm[];
    __shared__ int tok_s[BM];

    const int mt = blockIdx.y, nt = blockIdx.x;
    const int e = g_tile_expert[mt];
    const int tid = threadIdx.x;
    const int wid = tid >> 5, lane = tid & 31;
    const int wm = wid >> 2, wn = wid & 3;
    const uint32_t sb = s2u(dsm);

    if (tid < BM) tok_s[tid] = g_perm_token[mt * BM + tid];
    __syncthreads();

    float accg[2][4][4], accu[2][4][4];
#pragma unroll
    for (int i = 0; i < 2; i++)
#pragma unroll
        for (int j = 0; j < 4; j++)
#pragma unroll
            for (int q = 0; q < 4; q++) { accg[i][j][q] = 0.f; accu[i][j][q] = 0.f; }

    // prologue: fill S1-1 stages
    g1_load(0, 0, sb, tok_s, e, nt, tid);
    g1_load(1, 1, sb, tok_s, e, nt, tid);

    const int lrow = lane & 15;
    const int lcol = (lane >> 4) << 3;   // 0 or 8 halves

    for (int c = 0; c < NCH1; c++) {
        CP_WAIT(1);
        __syncthreads();
        if (c + 2 < NCH1) g1_load(c + 2, (c + 2) % S1, sb, tok_s, e, nt, tid);
        else CP_COMMIT();

        uint32_t sA  = sb + (c % S1) * STG1;
        uint32_t sBg = sA + TB;
        uint32_t sBu = sA + 2 * TB;
#pragma unroll
        for (int kk = 0; kk < 2; kk++) {
            const int cb = (kk * 16 + lcol) * 2;
            uint32_t a[2][4];
            ldsm4(a[0], sA + (wm * 32 + 0  + lrow) * (ROWH * 2) + cb);
            ldsm4(a[1], sA + (wm * 32 + 16 + lrow) * (ROWH * 2) + cb);
            uint32_t bg[2][4], bu[2][4];
            ldsm4(bg[0], sBg + (wn * 32 + 0  + lrow) * (ROWH * 2) + cb);
            ldsm4(bg[1], sBg + (wn * 32 + 16 + lrow) * (ROWH * 2) + cb);
            ldsm4(bu[0], sBu + (wn * 32 + 0  + lrow) * (ROWH * 2) + cb);
            ldsm4(bu[1], sBu + (wn * 32 + 16 + lrow) * (ROWH * 2) + cb);
#pragma unroll
            for (int im = 0; im < 2; im++) {
                mma16816(accg[im][0], a[im], bg[0][0], bg[0][2]);
                mma16816(accg[im][1], a[im], bg[0][1], bg[0][3]);
                mma16816(accg[im][2], a[im], bg[1][0], bg[1][2]);
                mma16816(accg[im][3], a[im], bg[1][1], bg[1][3]);
                mma16816(accu[im][0], a[im], bu[0][0], bu[0][2]);
                mma16816(accu[im][1], a[im], bu[0][1], bu[0][3]);
                mma16816(accu[im][2], a[im], bu[1][0], bu[1][2]);
                mma16816(accu[im][3], a[im], bu[1][1], bu[1][3]);
            }
        }
        __syncthreads();
    }

    // epilogue: act = silu(gate) * up -> fp16
    const int qr = lane >> 2, qc = lane & 3;
#pragma unroll
    for (int im = 0; im < 2; im++) {
#pragma unroll
        for (int jn = 0; jn < 4; jn++) {
            int r0 = mt * 128 + wm * 32 + im * 16 + qr;
            int col = nt * 128 + wn * 32 + jn * 8 + qc * 2;
#pragma unroll
            for (int h = 0; h < 2; h++) {  // h=0: rows qr, h=1: qr+8
                float g0 = accg[im][jn][2 * h + 0], g1 = accg[im][jn][2 * h + 1];
                float u0 = accu[im][jn][2 * h + 0], u1 = accu[im][jn][2 * h + 1];
                float a0 = g0 * u0 / (1.f + expf(-g0));
                float a1 = g1 * u1 / (1.f + expf(-g1));
                __half2* dst = (__half2*)(g_act + (size_t)(r0 + 8 * h) * INTERD + col);
                *dst = __floats2half2_rn(a0, a1);
            }
        }
    }
}

// =================== GEMM2: act @ w2t, weighted atomic scatter ==============
__device__ __forceinline__ void g2_load(int c, int slot, uint32_t sb,
                                        int mt, int e, int nt, int tid) {
    const int k0 = c * KSTEP;
#pragma unroll
    for (int it = 0; it < 2; it++) {
        int u = it * 512 + tid;
        int tile = u >> 9, v = u & 511;
        int row = v >> 2, ch = v & 3;
        uint32_t dst = sb + slot * STG2 + tile * TB + row * (ROWH * 2) + ch * 16;
        const __half* src;
        if (tile == 0)
            src = g_act + (size_t)(mt * 128 + row) * INTERD + k0 + ch * 8;
        else
            src = g_w2t + ((size_t)e * HID + nt * 128 + row) * INTERD + k0 + ch * 8;
        cp16(dst, src, 16);
    }
    CP_COMMIT();
}

__global__ void __launch_bounds__(512, 1) gemm2_kernel(float* __restrict__ out) {
    extern __shared__ __align__(128) char dsm[];
    __shared__ int tok_s[BM];
    __shared__ float w_s[BM];

    const int mt = blockIdx.y, nt = blockIdx.x;
    const int e = g_tile_expert[mt];
    const int tid = threadIdx.x;
    const int wid = tid >> 5, lane = tid & 31;
    const int wm = wid >> 2, wn = wid & 3;
    const uint32_t sb = s2u(dsm);

    if (tid < BM) { tok_s[tid] = g_perm_token[mt * BM + tid]; w_s[tid] = g_perm_w[mt * BM + tid]; }
    __syncthreads();

    float acc[2][4][4];
#pragma unroll
    for (int i = 0; i < 2; i++)
#pragma unroll
        for (int j = 0; j < 4; j++)
#pragma unroll
            for (int q = 0; q < 4; q++) acc[i][j][q] = 0.f;

    g2_load(0, 0, sb, mt, e, nt, tid);
    g2_load(1, 1, sb, mt, e, nt, tid);
    g2_load(2, 2, sb, mt, e, nt, tid);

    const int lrow = lane & 15;
    const int lcol = (lane >> 4) << 3;

    for (int c = 0; c < NCH2; c++) {
        CP_WAIT(2);
        __syncthreads();
        if (c + 3 < NCH2) g2_load(c + 3, (c + 3) % S2, sb, mt, e, nt, tid);
        else CP_COMMIT();

        uint32_t sA = sb + (c % S2) * STG2;
        uint32_t sB = sA + TB;
#pragma unroll
        for (int kk = 0; kk < 2; kk++) {
            const int cb = (kk * 16 + lcol) * 2;
            uint32_t a[2][4];
            ldsm4(a[0], sA + (wm * 32 + 0  + lrow) * (ROWH * 2) + cb);
            ldsm4(a[1], sA + (wm * 32 + 16 + lrow) * (ROWH * 2) + cb);
            uint32_t b[2][4];
            ldsm4(b[0], sB + (wn * 32 + 0  + lrow) * (ROWH * 2) + cb);
            ldsm4(b[1], sB + (wn * 32 + 16 + lrow) * (ROWH * 2) + cb);
#pragma unroll
            for (int im = 0; im < 2; im++) {
                mma16816(acc[im][0], a[im], b[0][0], b[0][2]);
                mma16816(acc[im][1], a[im], b[0][1], b[0][3]);
                mma16816(acc[im][2], a[im], b[1][0], b[1][2]);
                mma16816(acc[im][3], a[im], b[1][1], b[1][3]);
            }
        }
        __syncthreads();
    }

    const int qr = lane >> 2, qc = lane & 3;
#pragma unroll
    for (int im = 0; im < 2; im++) {
        int rl0 = wm * 32 + im * 16 + qr;
        int tok0 = tok_s[rl0],     tok1 = tok_s[rl0 + 8];
        float w0 = w_s[rl0],       w1v = w_s[rl0 + 8];
#pragma unroll
        for (int jn = 0; jn < 4; jn++) {
            int col = nt * 128 + wn * 32 + jn * 8 + qc * 2;
            if (tok0 >= 0) {
                float* op = out + (size_t)tok0 * HID + col;
                atomicAdd(op,     w0 * acc[im][jn][0]);
                atomicAdd(op + 1, w0 * acc[im][jn][1]);
            }
            if (tok1 >= 0) {
                float* op = out + (size_t)tok1 * HID + col;
                atomicAdd(op,     w1v * acc[im][jn][2]);
                atomicAdd(op + 1, w1v * acc[im][jn][3]);
            }
        }
    }
}

// ---------------- launch ----------------
extern "C" void kernel_launch(void* const* d_in, const int* in_sizes, int n_in,
                              void* d_out, int out_size) {
    const float* x  = (const float*)d_in[0];
    const float* gw = (const float*)d_in[1];
    const float* w1 = (const float*)d_in[2];
    const float* w2 = (const float*)d_in[3];
    float* out = (float*)d_out;

    cudaFuncSetAttribute(gemm1_kernel, cudaFuncAttributeMaxDynamicSharedMemorySize, S1 * STG1);
    cudaFuncSetAttribute(gemm2_kernel, cudaFuncAttributeMaxDynamicSharedMemorySize, S2 * STG2);

    init_kernel<<<256, 256>>>(out);
    convert_x_kernel<<<4096, 256>>>(x);
    transpose_w1_kernel<<<dim3(N1 / 32, HID / 32, NEXP), dim3(32, 8)>>>(w1);
    transpose_w2_kernel<<<dim3(INTERD / 32, HID / 32, NEXP), dim3(32, 8)>>>(w2);
    gate_kernel<<<NUM_TOK / 8, 256>>>(x, gw);
    scan_kernel<<<1, 1>>>();
    scatter_kernel<<<NROWS / 256, 256>>>();
    gemm1_kernel<<<dim3(INTERD / 128, NTILES), 512, S1 * STG1>>>();
    gemm2_kernel<<<dim3(HID / 128, NTILES), 512, S2 * STG2>>>(out);
}

// round 4
// speedup vs baseline: 6.1312x; 1.2440x over previous
#include <cuda_runtime.h>
#include <cuda_fp16.h>
#include <math.h>
#include <stdint.h>

#define NUM_TOK 8192
#define HID     1024
#define INTERD  2816
#define NEXP    8
#define NROWS   (NUM_TOK * 2)
#define BM      128
#define M_MAX   (NROWS + NEXP * BM)      // 17408
#define NTILES  (M_MAX / BM)             // 136
#define N1      (2 * INTERD)             // 5632

#define KSTEP   32
#define NCH1    (HID / KSTEP)            // 32
#define NCH2    (INTERD / KSTEP)         // 88

#define A_ROWB  80                        // 32 halves + 8 pad
#define ATILE   (128 * A_ROWB)            // 10240
#define B1_ROWB 272                       // 128 halves + 8 pad
#define B1TILE  (32 * B1_ROWB)            // 8704
#define STG1    (ATILE + 2 * B1TILE)      // 27648
#define B2_ROWB 528                       // 256 halves + 8 pad
#define B2TILE  (32 * B2_ROWB)            // 16896
#define STG2    (ATILE + B2TILE)          // 27136
#define S1      4
#define S2      5

// ---------------- device scratch ----------------
__device__ int   g_perm_token[M_MAX];
__device__ float g_perm_w[M_MAX];
__device__ int   g_counts[NEXP];
__device__ int   g_offsets[NEXP];
__device__ int   g_fill[NEXP];
__device__ int   g_tile_expert[NTILES];
__device__ int   g_topk_i[NROWS];
__device__ float g_topk_w[NROWS];

__device__ __half g_x16[(size_t)NUM_TOK * HID];
__device__ __half g_w1h[(size_t)NEXP * HID * N1];     // [e][k][n] n-contig
__device__ __half g_w2h[(size_t)NEXP * INTERD * HID]; // [e][i][h] h-contig
__device__ __half g_act[(size_t)M_MAX * INTERD];      // [row][i]

// ---------------- ptx helpers ----------------
__device__ __forceinline__ uint32_t s2u(const void* p) {
    uint32_t a;
    asm("{ .reg .u64 t; cvta.to.shared.u64 t, %1; cvt.u32.u64 %0, t; }" : "=r"(a) : "l"(p));
    return a;
}
__device__ __forceinline__ void ldsm4(uint32_t* r, uint32_t addr) {
    asm volatile("ldmatrix.sync.aligned.m8n8.x4.shared.b16 {%0,%1,%2,%3}, [%4];"
                 : "=r"(r[0]), "=r"(r[1]), "=r"(r[2]), "=r"(r[3]) : "r"(addr));
}
__device__ __forceinline__ void ldsm4t(uint32_t* r, uint32_t addr) {
    asm volatile("ldmatrix.sync.aligned.m8n8.x4.trans.shared.b16 {%0,%1,%2,%3}, [%4];"
                 : "=r"(r[0]), "=r"(r[1]), "=r"(r[2]), "=r"(r[3]) : "r"(addr));
}
__device__ __forceinline__ void mma16816(float* d, const uint32_t* a,
                                         uint32_t b0, uint32_t b1) {
    asm volatile(
        "mma.sync.aligned.m16n8k16.row.col.f32.f16.f16.f32 "
        "{%0,%1,%2,%3}, {%4,%5,%6,%7}, {%8,%9}, {%0,%1,%2,%3};"
        : "+f"(d[0]), "+f"(d[1]), "+f"(d[2]), "+f"(d[3])
        : "r"(a[0]), "r"(a[1]), "r"(a[2]), "r"(a[3]), "r"(b0), "r"(b1));
}
__device__ __forceinline__ void cp16(uint32_t dst, const void* src, int sz) {
    asm volatile("cp.async.cg.shared.global [%0], [%1], 16, %2;"
                 :: "r"(dst), "l"(src), "r"(sz));
}
#define CP_COMMIT() asm volatile("cp.async.commit_group;" ::: "memory")
#define CP_WAIT(n)  asm volatile("cp.async.wait_group %0;" :: "n"(n) : "memory")

// ---------------- small kernels ----------------
__global__ void init_kernel(float* __restrict__ out) {
    int i = blockIdx.x * blockDim.x + threadIdx.x;
    int stride = gridDim.x * blockDim.x;
    if (i < NEXP) { g_counts[i] = 0; g_fill[i] = 0; }
    if (i < NTILES) g_tile_expert[i] = 0;
    for (int r = i; r < M_MAX; r += stride) { g_perm_token[r] = -1; g_perm_w[r] = 0.f; }
    float4 z = make_float4(0.f, 0.f, 0.f, 0.f);
    for (size_t j = i; j < (size_t)NUM_TOK * HID / 4; j += stride)
        ((float4*)out)[j] = z;
}

__global__ void convert_kernel(const float* __restrict__ src, __half* __restrict__ dst,
                               size_t n4) {
    size_t i = (size_t)blockIdx.x * blockDim.x + threadIdx.x;
    size_t stride = (size_t)gridDim.x * blockDim.x;
    for (size_t j = i; j < n4; j += stride) {
        float4 v = ((const float4*)src)[j];
        ((__half2*)dst)[2 * j]     = __floats2half2_rn(v.x, v.y);
        ((__half2*)dst)[2 * j + 1] = __floats2half2_rn(v.z, v.w);
    }
}

__global__ void gate_kernel(const float* __restrict__ x, const float* __restrict__ gw) {
    int warp = (blockIdx.x * blockDim.x + threadIdx.x) >> 5;
    int lane = threadIdx.x & 31;
    if (warp >= NUM_TOK) return;
    const float* xr = x + (size_t)warp * HID;
    float acc[NEXP];
#pragma unroll
    for (int e = 0; e < NEXP; e++) acc[e] = 0.f;
    for (int h = lane; h < HID; h += 32) {
        float xv = xr[h];
#pragma unroll
        for (int e = 0; e < NEXP; e++) acc[e] += xv * gw[e * HID + h];
    }
#pragma unroll
    for (int e = 0; e < NEXP; e++)
#pragma unroll
        for (int o = 16; o > 0; o >>= 1)
            acc[e] += __shfl_xor_sync(0xffffffffu, acc[e], o);
    if (lane == 0) {
        int i1 = 0;
#pragma unroll
        for (int e = 1; e < NEXP; e++) if (acc[e] > acc[i1]) i1 = e;
        int i2 = (i1 == 0) ? 1 : 0;
#pragma unroll
        for (int e = 0; e < NEXP; e++) if (e != i1 && acc[e] > acc[i2]) i2 = e;
        float d  = expf(acc[i2] - acc[i1]);
        g_topk_i[warp * 2] = i1;     g_topk_i[warp * 2 + 1] = i2;
        g_topk_w[warp * 2] = 1.f / (1.f + d);
        g_topk_w[warp * 2 + 1] = d / (1.f + d);
        atomicAdd(&g_counts[i1], 1); atomicAdd(&g_counts[i2], 1);
    }
}

__global__ void scan_kernel() {
    int off = 0;
    for (int e = 0; e < NEXP; e++) {
        g_offsets[e] = off;
        int padded = ((g_counts[e] + BM - 1) / BM) * BM;
        for (int t = 0; t < padded / BM; t++) g_tile_expert[off / BM + t] = e;
        off += padded;
    }
}

__global__ void scatter_kernel() {
    int i = blockIdx.x * blockDim.x + threadIdx.x;
    if (i >= NROWS) return;
    int e = g_topk_i[i];
    int pos = g_offsets[e] + atomicAdd(&g_fill[e], 1);
    g_perm_token[pos] = i >> 1;
    g_perm_w[pos] = g_topk_w[i];
}

// =================== GEMM1: fused gate/up + SiLU ===================
// CTA 128M x 128N(gate)+128N(up). 8 warps, warp tile 64M x 32N x {gate,up}.
__device__ __forceinline__ void g1_load(int c, int slot, uint32_t sb,
                                        const int* tok_s, int e, int nt, int tid) {
    const int k0 = c * KSTEP;
    const uint32_t base = sb + slot * STG1;
#pragma unroll
    for (int it = 0; it < 6; it++) {
        int u = it * 256 + tid;
        if (u < 512) {
            int row = u >> 2, ch = u & 3;
            int tok = tok_s[row];
            int sz = (tok < 0) ? 0 : 16;
            if (tok < 0) tok = 0;
            cp16(base + row * A_ROWB + ch * 16,
                 g_x16 + (size_t)tok * HID + k0 + ch * 8, sz);
        } else {
            int v = u - 512;
            int mat = v >> 9, w = v & 511;
            int row = w >> 4, ch = w & 15;
            const __half* src = g_w1h + ((size_t)e * HID + k0 + row) * N1
                                + mat * INTERD + nt * 128 + ch * 8;
            cp16(base + ATILE + mat * B1TILE + row * B1_ROWB + ch * 16, src, 16);
        }
    }
    CP_COMMIT();
}

__global__ void __launch_bounds__(256, 1) gemm1_kernel() {
    extern __shared__ __align__(128) char dsm[];
    __shared__ int tok_s[BM];

    const int mt = blockIdx.y, nt = blockIdx.x;
    const int e = g_tile_expert[mt];
    const int tid = threadIdx.x, wid = tid >> 5, lane = tid & 31;
    const int wm = wid >> 2, wn = wid & 3;
    const uint32_t sb = s2u(dsm);

    if (tid < BM) tok_s[tid] = g_perm_token[mt * BM + tid];
    __syncthreads();

    float accg[4][4][4], accu[4][4][4];
#pragma unroll
    for (int i = 0; i < 4; i++)
#pragma unroll
        for (int j = 0; j < 4; j++)
#pragma unroll
            for (int q = 0; q < 4; q++) { accg[i][j][q] = 0.f; accu[i][j][q] = 0.f; }

    g1_load(0, 0, sb, tok_s, e, nt, tid);
    g1_load(1, 1, sb, tok_s, e, nt, tid);
    g1_load(2, 2, sb, tok_s, e, nt, tid);

    const int lrow = lane & 15;
    const int lhi  = ((lane >> 4) << 3) * 2;   // byte offset: 0 or 16

    for (int c = 0; c < NCH1; c++) {
        CP_WAIT(2);
        __syncthreads();
        if (c + 3 < NCH1) g1_load(c + 3, (c + 3) & 3, sb, tok_s, e, nt, tid);
        else CP_COMMIT();

        uint32_t stA  = sb + (c & 3) * STG1;
        uint32_t stBg = stA + ATILE;
        uint32_t stBu = stBg + B1TILE;
#pragma unroll
        for (int kk = 0; kk < 2; kk++) {
            uint32_t a[4][4];
#pragma unroll
            for (int i = 0; i < 4; i++)
                ldsm4(a[i], stA + (wm * 64 + i * 16 + lrow) * A_ROWB + kk * 32 + lhi);
            uint32_t bg[2][4], bu[2][4];
#pragma unroll
            for (int g = 0; g < 2; g++) {
                uint32_t roff = (kk * 16 + lrow) * B1_ROWB + (wn * 32 + g * 16) * 2 + lhi;
                ldsm4t(bg[g], stBg + roff);
                ldsm4t(bu[g], stBu + roff);
            }
#pragma unroll
            for (int i = 0; i < 4; i++) {
                mma16816(accg[i][0], a[i], bg[0][0], bg[0][1]);
                mma16816(accg[i][1], a[i], bg[0][2], bg[0][3]);
                mma16816(accg[i][2], a[i], bg[1][0], bg[1][1]);
                mma16816(accg[i][3], a[i], bg[1][2], bg[1][3]);
                mma16816(accu[i][0], a[i], bu[0][0], bu[0][1]);
                mma16816(accu[i][1], a[i], bu[0][2], bu[0][3]);
                mma16816(accu[i][2], a[i], bu[1][0], bu[1][1]);
                mma16816(accu[i][3], a[i], bu[1][2], bu[1][3]);
            }
        }
    }

    // epilogue: act = silu(gate) * up -> fp16
    const int qr = lane >> 2, qc = lane & 3;
#pragma unroll
    for (int i = 0; i < 4; i++) {
        int r0 = mt * 128 + wm * 64 + i * 16 + qr;
#pragma unroll
        for (int j = 0; j < 4; j++) {
            int col = nt * 128 + wn * 32 + j * 8 + qc * 2;
            {
                float g0 = accg[i][j][0], g1 = accg[i][j][1];
                float u0 = accu[i][j][0], u1 = accu[i][j][1];
                float a0 = g0 * u0 / (1.f + expf(-g0));
                float a1 = g1 * u1 / (1.f + expf(-g1));
                *(__half2*)(g_act + (size_t)r0 * INTERD + col) = __floats2half2_rn(a0, a1);
            }
            {
                float g0 = accg[i][j][2], g1 = accg[i][j][3];
                float u0 = accu[i][j][2], u1 = accu[i][j][3];
                float a0 = g0 * u0 / (1.f + expf(-g0));
                float a1 = g1 * u1 / (1.f + expf(-g1));
                *(__half2*)(g_act + (size_t)(r0 + 8) * INTERD + col) = __floats2half2_rn(a0, a1);
            }
        }
    }
}

// =================== GEMM2: act @ w2, weighted atomic scatter ===============
// CTA 128M x 256N. 8 warps, warp tile 64M x 64N.
__device__ __forceinline__ void g2_load(int c, int slot, uint32_t sb,
                                        int mt, int e, int nt, int tid) {
    const int k0 = c * KSTEP;
    const uint32_t base = sb + slot * STG2;
#pragma unroll
    for (int it = 0; it < 6; it++) {
        int u = it * 256 + tid;
        if (u < 512) {
            int row = u >> 2, ch = u & 3;
            cp16(base + row * A_ROWB + ch * 16,
                 g_act + (size_t)(mt * 128 + row) * INTERD + k0 + ch * 8, 16);
        } else {
            int v = u - 512;
            int row = v >> 5, ch = v & 31;
            const __half* src = g_w2h + ((size_t)e * INTERD + k0 + row) * HID
                                + nt * 256 + ch * 8;
            cp16(base + ATILE + row * B2_ROWB + ch * 16, src, 16);
        }
    }
    CP_COMMIT();
}

__global__ void __launch_bounds__(256, 1) gemm2_kernel(float* __restrict__ out) {
    extern __shared__ __align__(128) char dsm[];
    __shared__ int tok_s[BM];
    __shared__ float w_s[BM];

    const int mt = blockIdx.y, nt = blockIdx.x;
    const int e = g_tile_expert[mt];
    const int tid = threadIdx.x, wid = tid >> 5, lane = tid & 31;
    const int wm = wid >> 2, wn = wid & 3;
    const uint32_t sb = s2u(dsm);

    if (tid < BM) { tok_s[tid] = g_perm_token[mt * BM + tid]; w_s[tid] = g_perm_w[mt * BM + tid]; }
    __syncthreads();

    float acc[4][8][4];
#pragma unroll
    for (int i = 0; i < 4; i++)
#pragma unroll
        for (int j = 0; j < 8; j++)
#pragma unroll
            for (int q = 0; q < 4; q++) acc[i][j][q] = 0.f;

    g2_load(0, 0, sb, mt, e, nt, tid);
    g2_load(1, 1, sb, mt, e, nt, tid);
    g2_load(2, 2, sb, mt, e, nt, tid);
    g2_load(3, 3, sb, mt, e, nt, tid);

    const int lrow = lane & 15;
    const int lhi  = ((lane >> 4) << 3) * 2;

    for (int c = 0; c < NCH2; c++) {
        CP_WAIT(3);
        __syncthreads();
        if (c + 4 < NCH2) g2_load(c + 4, (c + 4) % S2, sb, mt, e, nt, tid);
        else CP_COMMIT();

        uint32_t stA = sb + (c % S2) * STG2;
        uint32_t stB = stA + ATILE;
#pragma unroll
        for (int kk = 0; kk < 2; kk++) {
            uint32_t a[4][4];
#pragma unroll
            for (int i = 0; i < 4; i++)
                ldsm4(a[i], stA + (wm * 64 + i * 16 + lrow) * A_ROWB + kk * 32 + lhi);
            uint32_t bq[4][4];
#pragma unroll
            for (int g = 0; g < 4; g++)
                ldsm4t(bq[g], stB + (kk * 16 + lrow) * B2_ROWB
                              + (wn * 64 + g * 16) * 2 + lhi);
#pragma unroll
            for (int i = 0; i < 4; i++)
#pragma unroll
                for (int j = 0; j < 8; j++)
                    mma16816(acc[i][j], a[i], bq[j >> 1][(j & 1) * 2],
                             bq[j >> 1][(j & 1) * 2 + 1]);
        }
    }

    const int qr = lane >> 2, qc = lane & 3;
#pragma unroll
    for (int i = 0; i < 4; i++) {
        int rl = wm * 64 + i * 16 + qr;
        int tok0 = tok_s[rl], tok1 = tok_s[rl + 8];
        float w0 = w_s[rl],   w1v = w_s[rl + 8];
#pragma unroll
        for (int j = 0; j < 8; j++) {
            int col = nt * 256 + wn * 64 + j * 8 + qc * 2;
            if (tok0 >= 0) {
                float* op = out + (size_t)tok0 * HID + col;
                atomicAdd(op,     w0 * acc[i][j][0]);
                atomicAdd(op + 1, w0 * acc[i][j][1]);
            }
            if (tok1 >= 0) {
                float* op = out + (size_t)tok1 * HID + col;
                atomicAdd(op,     w1v * acc[i][j][2]);
                atomicAdd(op + 1, w1v * acc[i][j][3]);
            }
        }
    }
}

// ---------------- launch ----------------
extern "C" void kernel_launch(void* const* d_in, const int* in_sizes, int n_in,
                              void* d_out, int out_size) {
    const float* x  = (const float*)d_in[0];
    const float* gw = (const float*)d_in[1];
    const float* w1 = (const float*)d_in[2];
    const float* w2 = (const float*)d_in[3];
    float* out = (float*)d_out;

    static __half* p_x16 = nullptr;
    static __half* p_w1h = nullptr;
    static __half* p_w2h = nullptr;
    if (!p_x16) {
        cudaGetSymbolAddress((void**)&p_x16, g_x16);
        cudaGetSymbolAddress((void**)&p_w1h, g_w1h);
        cudaGetSymbolAddress((void**)&p_w2h, g_w2h);
        cudaFuncSetAttribute(gemm1_kernel, cudaFuncAttributeMaxDynamicSharedMemorySize, S1 * STG1);
        cudaFuncSetAttribute(gemm2_kernel, cudaFuncAttributeMaxDynamicSharedMemorySize, S2 * STG2);
    }

    init_kernel<<<256, 256>>>(out);
    convert_kernel<<<2048, 256>>>(x,  p_x16, (size_t)NUM_TOK * HID / 4);
    convert_kernel<<<4096, 256>>>(w1, p_w1h, (size_t)NEXP * HID * N1 / 4);
    convert_kernel<<<4096, 256>>>(w2, p_w2h, (size_t)NEXP * INTERD * HID / 4);
    gate_kernel<<<NUM_TOK / 8, 256>>>(x, gw);
    scan_kernel<<<1, 1>>>();
    scatter_kernel<<<NROWS / 256, 256>>>();
    gemm1_kernel<<<dim3(INTERD / 128, NTILES), 256, S1 * STG1>>>();
    gemm2_kernel<<<dim3(HID / 256, NTILES), 256, S2 * STG2>>>(out);
}

// round 5
// speedup vs baseline: 6.7105x; 1.0945x over previous
#include <cuda_runtime.h>
#include <cuda_fp16.h>
#include <math.h>
#include <stdint.h>

#define NUM_TOK 8192
#define HID     1024
#define INTERD  2816
#define NEXP    8
#define NROWS   (NUM_TOK * 2)
#define BM      128
#define M_MAX   (NROWS + NEXP * BM)      // 17408
#define NTILES  (M_MAX / BM)             // 136
#define N1      (2 * INTERD)             // 5632

#define KSTEP   64
#define NCH1    (HID / KSTEP)            // 16
#define NCH2    (INTERD / KSTEP)         // 44

#define A_ROWB  144                       // 64 halves + 8 pad = 72 halves
#define ATILE   (128 * A_ROWB)            // 18432
#define B1_ROWB 272                       // 128 halves + 8 pad
#define B1TILE  (64 * B1_ROWB)            // 17408
#define STG1    (ATILE + 2 * B1TILE)      // 53248
#define B2_ROWB 528                       // 256 halves + 8 pad
#define B2TILE  (64 * B2_ROWB)            // 33792
#define STG2    (ATILE + B2TILE)          // 52224
#define S1      3
#define S2      3

// ---------------- device scratch ----------------
__device__ int   g_perm_token[M_MAX];
__device__ float g_perm_w[M_MAX];
__device__ int   g_counts[NEXP];
__device__ int   g_offsets[NEXP];
__device__ int   g_fill[NEXP];
__device__ int   g_tile_expert[NTILES];
__device__ int   g_topk_i[NROWS];
__device__ float g_topk_w[NROWS];
__device__ int   g_inv[NROWS];            // (token,slot) -> perm position

__device__ __half g_x16[(size_t)NUM_TOK * HID];
__device__ __half g_w1h[(size_t)NEXP * HID * N1];     // [e][k][n]
__device__ __half g_w2h[(size_t)NEXP * INTERD * HID]; // [e][i][h]
__device__ __half g_act[(size_t)M_MAX * INTERD];      // [row][i]
__device__ float  g_y[(size_t)M_MAX * HID];           // weighted GEMM2 rows

// ---------------- ptx helpers ----------------
__device__ __forceinline__ uint32_t s2u(const void* p) {
    uint32_t a;
    asm("{ .reg .u64 t; cvta.to.shared.u64 t, %1; cvt.u32.u64 %0, t; }" : "=r"(a) : "l"(p));
    return a;
}
__device__ __forceinline__ void ldsm4(uint32_t* r, uint32_t addr) {
    asm volatile("ldmatrix.sync.aligned.m8n8.x4.shared.b16 {%0,%1,%2,%3}, [%4];"
                 : "=r"(r[0]), "=r"(r[1]), "=r"(r[2]), "=r"(r[3]) : "r"(addr));
}
__device__ __forceinline__ void ldsm4t(uint32_t* r, uint32_t addr) {
    asm volatile("ldmatrix.sync.aligned.m8n8.x4.trans.shared.b16 {%0,%1,%2,%3}, [%4];"
                 : "=r"(r[0]), "=r"(r[1]), "=r"(r[2]), "=r"(r[3]) : "r"(addr));
}
__device__ __forceinline__ void mma16816(float* d, const uint32_t* a,
                                         uint32_t b0, uint32_t b1) {
    asm volatile(
        "mma.sync.aligned.m16n8k16.row.col.f32.f16.f16.f32 "
        "{%0,%1,%2,%3}, {%4,%5,%6,%7}, {%8,%9}, {%0,%1,%2,%3};"
        : "+f"(d[0]), "+f"(d[1]), "+f"(d[2]), "+f"(d[3])
        : "r"(a[0]), "r"(a[1]), "r"(a[2]), "r"(a[3]), "r"(b0), "r"(b1));
}
__device__ __forceinline__ void cp16(uint32_t dst, const void* src, int sz) {
    asm volatile("cp.async.cg.shared.global [%0], [%1], 16, %2;"
                 :: "r"(dst), "l"(src), "r"(sz));
}
#define CP_COMMIT() asm volatile("cp.async.commit_group;" ::: "memory")
#define CP_WAIT(n)  asm volatile("cp.async.wait_group %0;" :: "n"(n) : "memory")

// ---------------- small kernels ----------------
__global__ void init_kernel() {
    int i = blockIdx.x * blockDim.x + threadIdx.x;
    int stride = gridDim.x * blockDim.x;
    if (i < NEXP) { g_counts[i] = 0; g_fill[i] = 0; }
    if (i < NTILES) g_tile_expert[i] = 0;
    for (int r = i; r < M_MAX; r += stride) { g_perm_token[r] = -1; g_perm_w[r] = 0.f; }
}

__global__ void convert_kernel(const float* __restrict__ src, __half* __restrict__ dst,
                               size_t n4) {
    size_t i = (size_t)blockIdx.x * blockDim.x + threadIdx.x;
    size_t stride = (size_t)gridDim.x * blockDim.x;
    for (size_t j = i; j < n4; j += stride) {
        float4 v = ((const float4*)src)[j];
        ((__half2*)dst)[2 * j]     = __floats2half2_rn(v.x, v.y);
        ((__half2*)dst)[2 * j + 1] = __floats2half2_rn(v.z, v.w);
    }
}

// gate + fused x fp32->fp16 convert (one warp per token)
__global__ void gate_kernel(const float* __restrict__ x, const float* __restrict__ gw) {
    int warp = (blockIdx.x * blockDim.x + threadIdx.x) >> 5;
    int lane = threadIdx.x & 31;
    if (warp >= NUM_TOK) return;
    const float* xr = x + (size_t)warp * HID;
    __half* xo = g_x16 + (size_t)warp * HID;
    float acc[NEXP];
#pragma unroll
    for (int e = 0; e < NEXP; e++) acc[e] = 0.f;
    for (int h = lane; h < HID; h += 32) {
        float xv = xr[h];
        xo[h] = __float2half(xv);
#pragma unroll
        for (int e = 0; e < NEXP; e++) acc[e] += xv * gw[e * HID + h];
    }
#pragma unroll
    for (int e = 0; e < NEXP; e++)
#pragma unroll
        for (int o = 16; o > 0; o >>= 1)
            acc[e] += __shfl_xor_sync(0xffffffffu, acc[e], o);
    if (lane == 0) {
        int i1 = 0;
#pragma unroll
        for (int e = 1; e < NEXP; e++) if (acc[e] > acc[i1]) i1 = e;
        int i2 = (i1 == 0) ? 1 : 0;
#pragma unroll
        for (int e = 0; e < NEXP; e++) if (e != i1 && acc[e] > acc[i2]) i2 = e;
        float d  = expf(acc[i2] - acc[i1]);
        g_topk_i[warp * 2] = i1;     g_topk_i[warp * 2 + 1] = i2;
        g_topk_w[warp * 2] = 1.f / (1.f + d);
        g_topk_w[warp * 2 + 1] = d / (1.f + d);
        atomicAdd(&g_counts[i1], 1); atomicAdd(&g_counts[i2], 1);
    }
}

__global__ void scan_kernel() {
    int off = 0;
    for (int e = 0; e < NEXP; e++) {
        g_offsets[e] = off;
        int padded = ((g_counts[e] + BM - 1) / BM) * BM;
        for (int t = 0; t < padded / BM; t++) g_tile_expert[off / BM + t] = e;
        off += padded;
    }
}

__global__ void scatter_kernel() {
    int i = blockIdx.x * blockDim.x + threadIdx.x;
    if (i >= NROWS) return;
    int e = g_topk_i[i];
    int pos = g_offsets[e] + atomicAdd(&g_fill[e], 1);
    g_perm_token[pos] = i >> 1;
    g_perm_w[pos] = g_topk_w[i];
    g_inv[i] = pos;
}

// out[t] = y[inv[2t]] + y[inv[2t+1]]
__global__ void combine_kernel(float* __restrict__ out) {
    int t = blockIdx.x;
    int h4 = threadIdx.x;               // 256 threads x float4 = 1024 floats
    size_t p0 = (size_t)g_inv[2 * t], p1 = (size_t)g_inv[2 * t + 1];
    float4 a = ((const float4*)(g_y + p0 * HID))[h4];
    float4 b = ((const float4*)(g_y + p1 * HID))[h4];
    float4 r = make_float4(a.x + b.x, a.y + b.y, a.z + b.z, a.w + b.w);
    ((float4*)(out + (size_t)t * HID))[h4] = r;
}

// =================== GEMM1: fused gate/up + SiLU ===================
__device__ __forceinline__ void g1_load(int c, int slot, uint32_t sb,
                                        const int* tok_s, int e, int nt, int tid) {
    const int k0 = c * KSTEP;
    const uint32_t base = sb + slot * STG1;
#pragma unroll
    for (int it = 0; it < 12; it++) {
        int u = it * 256 + tid;
        if (u < 1024) {
            int row = u >> 3, ch = u & 7;
            int tok = tok_s[row];
            int sz = (tok < 0) ? 0 : 16;
            if (tok < 0) tok = 0;
            cp16(base + row * A_ROWB + ch * 16,
                 g_x16 + (size_t)tok * HID + k0 + ch * 8, sz);
        } else {
            int v = u - 1024;
            int mat = v >> 10, w = v & 1023;
            int row = w >> 4, ch = w & 15;
            const __half* src = g_w1h + ((size_t)e * HID + k0 + row) * N1
                                + mat * INTERD + nt * 128 + ch * 8;
            cp16(base + ATILE + mat * B1TILE + row * B1_ROWB + ch * 16, src, 16);
        }
    }
    CP_COMMIT();
}

__global__ void __launch_bounds__(256, 1) gemm1_kernel() {
    extern __shared__ __align__(128) char dsm[];
    __shared__ int tok_s[BM];

    const int mt = blockIdx.y, nt = blockIdx.x;
    const int e = g_tile_expert[mt];
    const int tid = threadIdx.x, wid = tid >> 5, lane = tid & 31;
    const int wm = wid >> 2, wn = wid & 3;
    const uint32_t sb = s2u(dsm);

    if (tid < BM) tok_s[tid] = g_perm_token[mt * BM + tid];
    __syncthreads();

    float accg[4][4][4], accu[4][4][4];
#pragma unroll
    for (int i = 0; i < 4; i++)
#pragma unroll
        for (int j = 0; j < 4; j++)
#pragma unroll
            for (int q = 0; q < 4; q++) { accg[i][j][q] = 0.f; accu[i][j][q] = 0.f; }

    g1_load(0, 0, sb, tok_s, e, nt, tid);
    g1_load(1, 1, sb, tok_s, e, nt, tid);

    const int lrow = lane & 15;
    const int lhi  = (lane >> 4) * 16;   // byte offset 0 or 16

    for (int c = 0; c < NCH1; c++) {
        CP_WAIT(1);
        __syncthreads();
        if (c + 2 < NCH1) g1_load(c + 2, (c + 2) % S1, sb, tok_s, e, nt, tid);
        else CP_COMMIT();

        uint32_t stA  = sb + (c % S1) * STG1;
        uint32_t stBg = stA + ATILE;
        uint32_t stBu = stBg + B1TILE;
#pragma unroll
        for (int kk = 0; kk < 4; kk++) {
            uint32_t a[4][4];
#pragma unroll
            for (int i = 0; i < 4; i++)
                ldsm4(a[i], stA + (wm * 64 + i * 16 + lrow) * A_ROWB + kk * 32 + lhi);
            uint32_t bg[2][4], bu[2][4];
#pragma unroll
            for (int g = 0; g < 2; g++) {
                uint32_t roff = (kk * 16 + lrow) * B1_ROWB + (wn * 32 + g * 16) * 2 + lhi;
                ldsm4t(bg[g], stBg + roff);
                ldsm4t(bu[g], stBu + roff);
            }
#pragma unroll
            for (int i = 0; i < 4; i++) {
                mma16816(accg[i][0], a[i], bg[0][0], bg[0][1]);
                mma16816(accg[i][1], a[i], bg[0][2], bg[0][3]);
                mma16816(accg[i][2], a[i], bg[1][0], bg[1][1]);
                mma16816(accg[i][3], a[i], bg[1][2], bg[1][3]);
                mma16816(accu[i][0], a[i], bu[0][0], bu[0][1]);
                mma16816(accu[i][1], a[i], bu[0][2], bu[0][3]);
                mma16816(accu[i][2], a[i], bu[1][0], bu[1][1]);
                mma16816(accu[i][3], a[i], bu[1][2], bu[1][3]);
            }
        }
    }

    // epilogue: act = silu(gate) * up -> fp16
    const int qr = lane >> 2, qc = lane & 3;
#pragma unroll
    for (int i = 0; i < 4; i++) {
        int r0 = mt * 128 + wm * 64 + i * 16 + qr;
#pragma unroll
        for (int j = 0; j < 4; j++) {
            int col = nt * 128 + wn * 32 + j * 8 + qc * 2;
            {
                float g0 = accg[i][j][0], g1 = accg[i][j][1];
                float u0 = accu[i][j][0], u1 = accu[i][j][1];
                float a0 = g0 * u0 / (1.f + expf(-g0));
                float a1 = g1 * u1 / (1.f + expf(-g1));
                *(__half2*)(g_act + (size_t)r0 * INTERD + col) = __floats2half2_rn(a0, a1);
            }
            {
                float g0 = accg[i][j][2], g1 = accg[i][j][3];
                float u0 = accu[i][j][2], u1 = accu[i][j][3];
                float a0 = g0 * u0 / (1.f + expf(-g0));
                float a1 = g1 * u1 / (1.f + expf(-g1));
                *(__half2*)(g_act + (size_t)(r0 + 8) * INTERD + col) = __floats2half2_rn(a0, a1);
            }
        }
    }
}

// =================== GEMM2: act @ w2, weighted plain-store epilogue =========
__device__ __forceinline__ void g2_load(int c, int slot, uint32_t sb,
                                        int mt, int e, int nt, int tid) {
    const int k0 = c * KSTEP;
    const uint32_t base = sb + slot * STG2;
#pragma unroll
    for (int it = 0; it < 12; it++) {
        int u = it * 256 + tid;
        if (u < 1024) {
            int row = u >> 3, ch = u & 7;
            cp16(base + row * A_ROWB + ch * 16,
                 g_act + (size_t)(mt * 128 + row) * INTERD + k0 + ch * 8, 16);
        } else {
            int v = u - 1024;
            int row = v >> 5, ch = v & 31;
            const __half* src = g_w2h + ((size_t)e * INTERD + k0 + row) * HID
                                + nt * 256 + ch * 8;
            cp16(base + ATILE + row * B2_ROWB + ch * 16, src, 16);
        }
    }
    CP_COMMIT();
}

__global__ void __launch_bounds__(256, 1) gemm2_kernel() {
    extern __shared__ __align__(128) char dsm[];
    __shared__ float w_s[BM];

    const int mt = blockIdx.y, nt = blockIdx.x;
    const int e = g_tile_expert[mt];
    const int tid = threadIdx.x, wid = tid >> 5, lane = tid & 31;
    const int wm = wid >> 2, wn = wid & 3;
    const uint32_t sb = s2u(dsm);

    if (tid < BM) w_s[tid] = g_perm_w[mt * BM + tid];
    __syncthreads();

    float acc[4][8][4];
#pragma unroll
    for (int i = 0; i < 4; i++)
#pragma unroll
        for (int j = 0; j < 8; j++)
#pragma unroll
            for (int q = 0; q < 4; q++) acc[i][j][q] = 0.f;

    g2_load(0, 0, sb, mt, e, nt, tid);
    g2_load(1, 1, sb, mt, e, nt, tid);

    const int lrow = lane & 15;
    const int lhi  = (lane >> 4) * 16;

    for (int c = 0; c < NCH2; c++) {
        CP_WAIT(1);
        __syncthreads();
        if (c + 2 < NCH2) g2_load(c + 2, (c + 2) % S2, sb, mt, e, nt, tid);
        else CP_COMMIT();

        uint32_t stA = sb + (c % S2) * STG2;
        uint32_t stB = stA + ATILE;
#pragma unroll
        for (int kk = 0; kk < 4; kk++) {
            uint32_t a[4][4];
#pragma unroll
            for (int i = 0; i < 4; i++)
                ldsm4(a[i], stA + (wm * 64 + i * 16 + lrow) * A_ROWB + kk * 32 + lhi);
            uint32_t bq[4][4];
#pragma unroll
            for (int g = 0; g < 4; g++)
                ldsm4t(bq[g], stB + (kk * 16 + lrow) * B2_ROWB
                              + (wn * 64 + g * 16) * 2 + lhi);
#pragma unroll
            for (int i = 0; i < 4; i++)
#pragma unroll
                for (int j = 0; j < 8; j++)
                    mma16816(acc[i][j], a[i], bq[j >> 1][(j & 1) * 2],
                             bq[j >> 1][(j & 1) * 2 + 1]);
        }
    }

    // epilogue: plain weighted stores to g_y (rows unique -> no atomics)
    const int qr = lane >> 2, qc = lane & 3;
#pragma unroll
    for (int i = 0; i < 4; i++) {
        int rl = wm * 64 + i * 16 + qr;
        size_t r0 = (size_t)(mt * 128 + rl);
        float w0 = w_s[rl], w1v = w_s[rl + 8];
#pragma unroll
        for (int j = 0; j < 8; j++) {
            int col = nt * 256 + wn * 64 + j * 8 + qc * 2;
            *(float2*)(g_y + r0 * HID + col) =
                make_float2(w0 * acc[i][j][0], w0 * acc[i][j][1]);
            *(float2*)(g_y + (r0 + 8) * HID + col) =
                make_float2(w1v * acc[i][j][2], w1v * acc[i][j][3]);
        }
    }
}

// ---------------- launch ----------------
extern "C" void kernel_launch(void* const* d_in, const int* in_sizes, int n_in,
                              void* d_out, int out_size) {
    const float* x  = (const float*)d_in[0];
    const float* gw = (const float*)d_in[1];
    const float* w1 = (const float*)d_in[2];
    const float* w2 = (const float*)d_in[3];
    float* out = (float*)d_out;

    static __half* p_w1h = nullptr;
    static __half* p_w2h = nullptr;
    if (!p_w1h) {
        cudaGetSymbolAddress((void**)&p_w1h, g_w1h);
        cudaGetSymbolAddress((void**)&p_w2h, g_w2h);
        cudaFuncSetAttribute(gemm1_kernel, cudaFuncAttributeMaxDynamicSharedMemorySize, S1 * STG1);
        cudaFuncSetAttribute(gemm2_kernel, cudaFuncAttributeMaxDynamicSharedMemorySize, S2 * STG2);
    }

    init_kernel<<<136, 256>>>();
    convert_kernel<<<4096, 256>>>(w1, p_w1h, (size_t)NEXP * HID * N1 / 4);
    convert_kernel<<<4096, 256>>>(w2, p_w2h, (size_t)NEXP * INTERD * HID / 4);
    gate_kernel<<<NUM_TOK / 8, 256>>>(x, gw);
    scan_kernel<<<1, 1>>>();
    scatter_kernel<<<NROWS / 256, 256>>>();
    gemm1_kernel<<<dim3(INTERD / 128, NTILES), 256, S1 * STG1>>>();
    gemm2_kernel<<<dim3(HID / 256, NTILES), 256, S2 * STG2>>>();
    combine_kernel<<<NUM_TOK, 256>>>(out);
}